// round 3
// baseline (speedup 1.0000x reference)
#include <cuda_runtime.h>

#define NN 100000
#define NE 3200000
#define NF 128
#define NH 16
#define MH 100
#define NC 12
#define NG 512

// ---- device scratch (static, no allocation; 16B-aligned for v4 RED/loads) ----
__device__ __align__(16) int2  g_edge[NE];        // packed (src, dst) int32
__device__ __align__(16) int   g_deg[NN];
__device__ __align__(16) float g_dinv[NN];
__device__ __align__(16) float g_hpre[NN * NH];   // x @ W1
__device__ __align__(16) float g_acc1[NN * NH];   // layer-1 aggregation
__device__ __align__(16) float g_hpre2[NN * NH];  // h1 @ W2
__device__ __align__(16) float g_acc2[NN * NH];   // layer-2 aggregation
__device__ __align__(16) float g_pooled[NG * NH];
__device__ int g_is64;   // 1 if index inputs are int64, 0 if int32

__device__ __forceinline__ void red4(float* p, float4 v) {
    asm volatile("red.global.add.v4.f32 [%0], {%1,%2,%3,%4};"
                 :: "l"(p), "f"(v.x), "f"(v.y), "f"(v.z), "f"(v.w)
                 : "memory");
}

// ---- dtype probe: int64 buffers viewed as int32 are [v,0,v,0,...] ----
__global__ void k_detect(const int* __restrict__ ei32) {
    // single thread; reads first 512B only (in-bounds for either dtype)
    int any_nonzero = 0;
    for (int i = 1; i < 128; i += 2) any_nonzero |= ei32[i];
    g_is64 = (any_nonzero == 0) ? 1 : 0;
}

// ---- zero all accumulators ----
__global__ void k_zero() {
    int i = blockIdx.x * blockDim.x + threadIdx.x;
    int stride = gridDim.x * blockDim.x;
    float4 z = make_float4(0.f, 0.f, 0.f, 0.f);
    for (int j = i; j < NN * NH / 4; j += stride) {
        ((float4*)g_acc1)[j] = z;
        ((float4*)g_acc2)[j] = z;
    }
    for (int j = i; j < NN; j += stride) g_deg[j] = 0;
    if (i < NG * NH) g_pooled[i] = 0.f;
}

// ---- degree count + index -> int2 conversion (dtype-agnostic) ----
__global__ void k_deg(const void* __restrict__ ei) {
    int e = blockIdx.x * blockDim.x + threadIdx.x;
    if (e >= NE) return;
    int s, d;
    if (g_is64) {
        const long long* p = (const long long*)ei;
        s = (int)p[e];
        d = (int)p[NE + e];
    } else {
        const int* p = (const int*)ei;
        s = p[e];
        d = p[NE + e];
    }
    g_edge[e] = make_int2(s, d);
    atomicAdd(&g_deg[d], 1);
}

// ---- dinv = rsqrt(deg + 1 self loop) ----
__global__ void k_dinv() {
    int i = blockIdx.x * blockDim.x + threadIdx.x;
    if (i < NN) g_dinv[i] = rsqrtf((float)(g_deg[i] + 1));
}

// ---- hpre = x @ W1  (100K x 128 x 16) ----
__global__ void k_gemm1(const float* __restrict__ x, const float* __restrict__ W1) {
    __shared__ float w[NF * NH];
    for (int i = threadIdx.x; i < NF * NH; i += blockDim.x) w[i] = W1[i];
    __syncthreads();
    int r = blockIdx.x * blockDim.x + threadIdx.x;
    if (r >= NN) return;
    float acc[NH];
#pragma unroll
    for (int j = 0; j < NH; j++) acc[j] = 0.f;
    const float4* xr = (const float4*)(x + (size_t)r * NF);
    for (int k4 = 0; k4 < NF / 4; k4++) {
        float4 v = __ldg(xr + k4);
        const float* wr = w + k4 * 4 * NH;
#pragma unroll
        for (int j = 0; j < NH; j++)
            acc[j] += v.x * wr[j] + v.y * wr[NH + j] + v.z * wr[2 * NH + j] + v.w * wr[3 * NH + j];
    }
    float4* o = (float4*)(g_hpre + (size_t)r * NH);
#pragma unroll
    for (int j4 = 0; j4 < NH / 4; j4++)
        o[j4] = make_float4(acc[4 * j4], acc[4 * j4 + 1], acc[4 * j4 + 2], acc[4 * j4 + 3]);
}

// ---- edge scatter: acc[dst] += h[src] * dinv[src]*dinv[dst] ----
template <int LAYER>
__global__ void k_edge() {
    int e = blockIdx.x * blockDim.x + threadIdx.x;
    if (e >= NE) return;
    int2 sd = g_edge[e];
    float wgt = g_dinv[sd.x] * g_dinv[sd.y];
    const float4* hin = (const float4*)((LAYER == 1 ? g_hpre : g_hpre2) + (size_t)sd.x * NH);
    float* out = (LAYER == 1 ? g_acc1 : g_acc2) + (size_t)sd.y * NH;
#pragma unroll
    for (int q = 0; q < NH / 4; q++) {
        float4 v = __ldg(hin + q);
        v.x *= wgt; v.y *= wgt; v.z *= wgt; v.w *= wgt;
        red4(out + 4 * q, v);
    }
}

// ---- finalize layer 1: h1 = relu(acc1 + self + b1); hpre2 = h1 @ W2 ----
__global__ void k_fin1(const float* __restrict__ b1, const float* __restrict__ W2) {
    __shared__ float w2[NH * NH];
    __shared__ float bs[NH];
    if (threadIdx.x < NH * NH) w2[threadIdx.x] = W2[threadIdx.x];
    if (threadIdx.x < NH) bs[threadIdx.x] = b1[threadIdx.x];
    __syncthreads();
    int r = blockIdx.x * blockDim.x + threadIdx.x;
    if (r >= NN) return;
    float di = g_dinv[r];
    float sw = di * di;
    float h[NH];
#pragma unroll
    for (int j4 = 0; j4 < 4; j4++) {
        float4 a = *(const float4*)(g_acc1 + (size_t)r * NH + 4 * j4);
        float4 p = *(const float4*)(g_hpre + (size_t)r * NH + 4 * j4);
        h[4 * j4 + 0] = fmaxf(fmaf(p.x, sw, a.x) + bs[4 * j4 + 0], 0.f);
        h[4 * j4 + 1] = fmaxf(fmaf(p.y, sw, a.y) + bs[4 * j4 + 1], 0.f);
        h[4 * j4 + 2] = fmaxf(fmaf(p.z, sw, a.z) + bs[4 * j4 + 2], 0.f);
        h[4 * j4 + 3] = fmaxf(fmaf(p.w, sw, a.w) + bs[4 * j4 + 3], 0.f);
    }
    float o[NH];
#pragma unroll
    for (int j = 0; j < NH; j++) o[j] = 0.f;
#pragma unroll
    for (int j = 0; j < NH; j++) {
        float hj = h[j];
#pragma unroll
        for (int j2 = 0; j2 < NH; j2++) o[j2] += hj * w2[j * NH + j2];
    }
    float4* od = (float4*)(g_hpre2 + (size_t)r * NH);
#pragma unroll
    for (int j4 = 0; j4 < 4; j4++)
        od[j4] = make_float4(o[4 * j4], o[4 * j4 + 1], o[4 * j4 + 2], o[4 * j4 + 3]);
}

// ---- finalize layer 2 + global_add_pool (dtype-agnostic batch) ----
__global__ void k_fin2(const float* __restrict__ b2, const void* __restrict__ batch) {
    __shared__ float bs[NH];
    if (threadIdx.x < NH) bs[threadIdx.x] = b2[threadIdx.x];
    __syncthreads();
    int r = blockIdx.x * blockDim.x + threadIdx.x;
    if (r >= NN) return;
    float di = g_dinv[r];
    float sw = di * di;
    int b = g_is64 ? (int)((const long long*)batch)[r] : ((const int*)batch)[r];
    float* pool = g_pooled + (size_t)b * NH;
#pragma unroll
    for (int j4 = 0; j4 < 4; j4++) {
        float4 a = *(const float4*)(g_acc2 + (size_t)r * NH + 4 * j4);
        float4 p = *(const float4*)(g_hpre2 + (size_t)r * NH + 4 * j4);
        float4 v;
        v.x = fmaxf(fmaf(p.x, sw, a.x) + bs[4 * j4 + 0], 0.f);
        v.y = fmaxf(fmaf(p.y, sw, a.y) + bs[4 * j4 + 1], 0.f);
        v.z = fmaxf(fmaf(p.z, sw, a.z) + bs[4 * j4 + 2], 0.f);
        v.w = fmaxf(fmaf(p.w, sw, a.w) + bs[4 * j4 + 3], 0.f);
        red4(pool + 4 * j4, v);
    }
}

// ---- MLP head: relu(pool) -> relu(@lw1+lb1) -> @lw2+lb2 ----
__global__ void k_head(const float* __restrict__ lw1, const float* __restrict__ lb1,
                       const float* __restrict__ lw2, const float* __restrict__ lb2,
                       float* __restrict__ out) {
    __shared__ float w1s[NH * MH];
    __shared__ float w2s[MH * NC];
    __shared__ float b1s[MH];
    __shared__ float b2s[NC];
    for (int i = threadIdx.x; i < NH * MH; i += blockDim.x) w1s[i] = lw1[i];
    for (int i = threadIdx.x; i < MH * NC; i += blockDim.x) w2s[i] = lw2[i];
    if (threadIdx.x < MH) b1s[threadIdx.x] = lb1[threadIdx.x];
    if (threadIdx.x < NC) b2s[threadIdx.x] = lb2[threadIdx.x];
    __syncthreads();
    int g = blockIdx.x * blockDim.x + threadIdx.x;
    if (g >= NG) return;
    float p[NH];
#pragma unroll
    for (int j = 0; j < NH; j++) p[j] = fmaxf(g_pooled[g * NH + j], 0.f);
    float o[NC];
#pragma unroll
    for (int c = 0; c < NC; c++) o[c] = b2s[c];
    for (int m = 0; m < MH; m++) {
        float hh = b1s[m];
#pragma unroll
        for (int j = 0; j < NH; j++) hh += p[j] * w1s[j * MH + m];
        hh = fmaxf(hh, 0.f);
#pragma unroll
        for (int c = 0; c < NC; c++) o[c] += hh * w2s[m * NC + c];
    }
#pragma unroll
    for (int c = 0; c < NC; c++) out[g * NC + c] = o[c];
}

extern "C" void kernel_launch(void* const* d_in, const int* in_sizes, int n_in,
                              void* d_out, int out_size) {
    // Map inputs by element count (all distinct except b1/b2 which are
    // disambiguated by order of appearance).
    const float* x = nullptr;
    const void*  ei = nullptr;
    const void*  batch = nullptr;
    const float *W1 = nullptr, *b1 = nullptr, *W2 = nullptr, *b2 = nullptr;
    const float *lw1 = nullptr, *lb1 = nullptr, *lw2 = nullptr, *lb2 = nullptr;
    for (int i = 0; i < n_in; i++) {
        int sz = in_sizes[i];
        const void* p = d_in[i];
        switch (sz) {
            case NN * NF:   x     = (const float*)p; break;
            case 2 * NE:    ei    = p; break;
            case NN:        batch = p; break;
            case NF * NH:   W1    = (const float*)p; break;
            case NH * NH:   W2    = (const float*)p; break;
            case NH * MH:   lw1   = (const float*)p; break;
            case MH:        lb1   = (const float*)p; break;
            case MH * NC:   lw2   = (const float*)p; break;
            case NC:        lb2   = (const float*)p; break;
            case NH:        if (!b1) b1 = (const float*)p; else b2 = (const float*)p; break;
            default: break;
        }
    }
    float* out = (float*)d_out;

    k_detect<<<1, 1>>>((const int*)ei);
    k_zero<<<2048, 256>>>();
    k_deg<<<(NE + 255) / 256, 256>>>(ei);
    k_dinv<<<(NN + 255) / 256, 256>>>();
    k_gemm1<<<(NN + 255) / 256, 256>>>(x, W1);
    k_edge<1><<<(NE + 255) / 256, 256>>>();
    k_fin1<<<(NN + 255) / 256, 256>>>(b1, W2);
    k_edge<2><<<(NE + 255) / 256, 256>>>();
    k_fin2<<<(NN + 255) / 256, 256>>>(b2, batch);
    k_head<<<(NG + 255) / 256, 256>>>(lw1, lb1, lw2, lb2, out);
}

// round 4
// speedup vs baseline: 1.5127x; 1.5127x over previous
#include <cuda_runtime.h>

#define NN 100000
#define NE 3200000
#define NF 128
#define NH 16
#define MH 100
#define NC 12
#define NG 512
#define NBLK 391   // ceil(NN/256)

// ---- device scratch (static, no allocation; 16B-aligned) ----
__device__ __align__(16) int2  g_csr[NE];         // {src, norm-as-bits}
__device__ __align__(16) int   g_deg[NN];
__device__ __align__(16) int   g_rowstart[NN];
__device__ __align__(16) int   g_cursor[NN];
__device__ __align__(16) int   g_blocksum[512];
__device__ __align__(16) int   g_blockoff[512];
__device__ __align__(16) float g_dinv[NN];
__device__ __align__(16) float g_hpre[NN * NH];   // x @ W1
__device__ __align__(16) float g_acc1[NN * NH];
__device__ __align__(16) float g_hpre2[NN * NH];  // h1 @ W2
__device__ __align__(16) float g_acc2[NN * NH];
__device__ __align__(16) float g_pooled[NG * NH];
__device__ int g_is64;

__device__ __forceinline__ void red4(float* p, float4 v) {
    asm volatile("red.global.add.v4.f32 [%0], {%1,%2,%3,%4};"
                 :: "l"(p), "f"(v.x), "f"(v.y), "f"(v.z), "f"(v.w)
                 : "memory");
}

// ---- dtype probe: int64 buffers viewed as int32 are [v,0,v,0,...] ----
__global__ void k_detect(const int* __restrict__ ei32) {
    int any_nonzero = 0;
    for (int i = 1; i < 128; i += 2) any_nonzero |= ei32[i];
    g_is64 = (any_nonzero == 0) ? 1 : 0;
}

// ---- zero small state (acc arrays no longer need zeroing: k_agg overwrites) ----
__global__ void k_zero() {
    int i = blockIdx.x * blockDim.x + threadIdx.x;
    int stride = gridDim.x * blockDim.x;
    for (int j = i; j < NN; j += stride) g_deg[j] = 0;
    if (i < NG * NH) g_pooled[i] = 0.f;
}

// ---- degree count (reads dst column only) ----
__global__ void k_deg(const void* __restrict__ ei) {
    int e = blockIdx.x * blockDim.x + threadIdx.x;
    if (e >= NE) return;
    int d = g_is64 ? (int)((const long long*)ei)[NE + e]
                   : ((const int*)ei)[NE + e];
    atomicAdd(&g_deg[d], 1);
}

// ---- 3-stage exclusive prefix scan of g_deg -> g_rowstart / g_cursor ----
__global__ void k_scan1() {
    __shared__ int s[256];
    int i = blockIdx.x * 256 + threadIdx.x;
    s[threadIdx.x] = (i < NN) ? g_deg[i] : 0;
    __syncthreads();
    for (int o = 128; o > 0; o >>= 1) {
        if (threadIdx.x < o) s[threadIdx.x] += s[threadIdx.x + o];
        __syncthreads();
    }
    if (threadIdx.x == 0) g_blocksum[blockIdx.x] = s[0];
}
__global__ void k_scan2() {
    __shared__ int s[512];
    int t = threadIdx.x;
    int own = (t < NBLK) ? g_blocksum[t] : 0;
    s[t] = own;
    __syncthreads();
    for (int o = 1; o < 512; o <<= 1) {
        int v = (t >= o) ? s[t - o] : 0;
        __syncthreads();
        s[t] += v;
        __syncthreads();
    }
    if (t < NBLK) g_blockoff[t] = s[t] - own;  // exclusive
}
__global__ void k_scan3() {
    __shared__ int s[256];
    int t = threadIdx.x;
    int i = blockIdx.x * 256 + t;
    int d = (i < NN) ? g_deg[i] : 0;
    s[t] = d;
    __syncthreads();
    for (int o = 1; o < 256; o <<= 1) {
        int v = (t >= o) ? s[t - o] : 0;
        __syncthreads();
        s[t] += v;
        __syncthreads();
    }
    if (i < NN) {
        int start = g_blockoff[blockIdx.x] + s[t] - d;  // exclusive
        g_rowstart[i] = start;
        g_cursor[i]   = start;
    }
}

// ---- dinv = rsqrt(deg + 1 self loop) ----
__global__ void k_dinv() {
    int i = blockIdx.x * blockDim.x + threadIdx.x;
    if (i < NN) g_dinv[i] = rsqrtf((float)(g_deg[i] + 1));
}

// ---- CSR fill: csr[slot] = {src, dinv[src]*dinv[dst]} ----
__global__ void k_fill(const void* __restrict__ ei) {
    int e = blockIdx.x * blockDim.x + threadIdx.x;
    if (e >= NE) return;
    int s, d;
    if (g_is64) {
        const long long* p = (const long long*)ei;
        s = (int)p[e];
        d = (int)p[NE + e];
    } else {
        const int* p = (const int*)ei;
        s = p[e];
        d = p[NE + e];
    }
    float nrm = g_dinv[s] * g_dinv[d];
    int slot = atomicAdd(&g_cursor[d], 1);
    g_csr[slot] = make_int2(s, __float_as_int(nrm));
}

// ---- hpre = x @ W1  (100K x 128 x 16) ----
__global__ void k_gemm1(const float* __restrict__ x, const float* __restrict__ W1) {
    __shared__ float w[NF * NH];
    for (int i = threadIdx.x; i < NF * NH; i += blockDim.x) w[i] = W1[i];
    __syncthreads();
    int r = blockIdx.x * blockDim.x + threadIdx.x;
    if (r >= NN) return;
    float acc[NH];
#pragma unroll
    for (int j = 0; j < NH; j++) acc[j] = 0.f;
    const float4* xr = (const float4*)(x + (size_t)r * NF);
    for (int k4 = 0; k4 < NF / 4; k4++) {
        float4 v = __ldg(xr + k4);
        const float* wr = w + k4 * 4 * NH;
#pragma unroll
        for (int j = 0; j < NH; j++)
            acc[j] += v.x * wr[j] + v.y * wr[NH + j] + v.z * wr[2 * NH + j] + v.w * wr[3 * NH + j];
    }
    float4* o = (float4*)(g_hpre + (size_t)r * NH);
#pragma unroll
    for (int j4 = 0; j4 < NH / 4; j4++)
        o[j4] = make_float4(acc[4 * j4], acc[4 * j4 + 1], acc[4 * j4 + 2], acc[4 * j4 + 3]);
}

// ---- CSR aggregation (atomic-free): 4 threads per dst, float4 each ----
template <int LAYER>
__global__ void k_agg() {
    int tid = blockIdx.x * blockDim.x + threadIdx.x;
    int dst = tid >> 2;
    int f4  = tid & 3;
    if (dst >= NN) return;
    int start = __ldg(&g_rowstart[dst]);
    int cnt   = __ldg(&g_deg[dst]);
    const float* hin = (LAYER == 1 ? g_hpre : g_hpre2);
    const int2* p = g_csr + start;
    float4 acc = make_float4(0.f, 0.f, 0.f, 0.f);
    int i = 0;
    for (; i + 1 < cnt; i += 2) {
        int2 e0 = __ldg(p + i);
        int2 e1 = __ldg(p + i + 1);
        float4 v0 = __ldg((const float4*)(hin + (size_t)e0.x * NH) + f4);
        float4 v1 = __ldg((const float4*)(hin + (size_t)e1.x * NH) + f4);
        float w0 = __int_as_float(e0.y);
        float w1 = __int_as_float(e1.y);
        acc.x += w0 * v0.x + w1 * v1.x;
        acc.y += w0 * v0.y + w1 * v1.y;
        acc.z += w0 * v0.z + w1 * v1.z;
        acc.w += w0 * v0.w + w1 * v1.w;
    }
    if (i < cnt) {
        int2 e0 = __ldg(p + i);
        float4 v0 = __ldg((const float4*)(hin + (size_t)e0.x * NH) + f4);
        float w0 = __int_as_float(e0.y);
        acc.x += w0 * v0.x; acc.y += w0 * v0.y;
        acc.z += w0 * v0.z; acc.w += w0 * v0.w;
    }
    float* outp = (LAYER == 1 ? g_acc1 : g_acc2);
    ((float4*)(outp + (size_t)dst * NH))[f4] = acc;
}

// ---- finalize layer 1: h1 = relu(acc1 + self + b1); hpre2 = h1 @ W2 ----
__global__ void k_fin1(const float* __restrict__ b1, const float* __restrict__ W2) {
    __shared__ float w2[NH * NH];
    __shared__ float bs[NH];
    if (threadIdx.x < NH * NH) w2[threadIdx.x] = W2[threadIdx.x];
    if (threadIdx.x < NH) bs[threadIdx.x] = b1[threadIdx.x];
    __syncthreads();
    int r = blockIdx.x * blockDim.x + threadIdx.x;
    if (r >= NN) return;
    float di = g_dinv[r];
    float sw = di * di;
    float h[NH];
#pragma unroll
    for (int j4 = 0; j4 < 4; j4++) {
        float4 a = *(const float4*)(g_acc1 + (size_t)r * NH + 4 * j4);
        float4 p = *(const float4*)(g_hpre + (size_t)r * NH + 4 * j4);
        h[4 * j4 + 0] = fmaxf(fmaf(p.x, sw, a.x) + bs[4 * j4 + 0], 0.f);
        h[4 * j4 + 1] = fmaxf(fmaf(p.y, sw, a.y) + bs[4 * j4 + 1], 0.f);
        h[4 * j4 + 2] = fmaxf(fmaf(p.z, sw, a.z) + bs[4 * j4 + 2], 0.f);
        h[4 * j4 + 3] = fmaxf(fmaf(p.w, sw, a.w) + bs[4 * j4 + 3], 0.f);
    }
    float o[NH];
#pragma unroll
    for (int j = 0; j < NH; j++) o[j] = 0.f;
#pragma unroll
    for (int j = 0; j < NH; j++) {
        float hj = h[j];
#pragma unroll
        for (int j2 = 0; j2 < NH; j2++) o[j2] += hj * w2[j * NH + j2];
    }
    float4* od = (float4*)(g_hpre2 + (size_t)r * NH);
#pragma unroll
    for (int j4 = 0; j4 < 4; j4++)
        od[j4] = make_float4(o[4 * j4], o[4 * j4 + 1], o[4 * j4 + 2], o[4 * j4 + 3]);
}

// ---- finalize layer 2 + global_add_pool ----
__global__ void k_fin2(const float* __restrict__ b2, const void* __restrict__ batch) {
    __shared__ float bs[NH];
    if (threadIdx.x < NH) bs[threadIdx.x] = b2[threadIdx.x];
    __syncthreads();
    int r = blockIdx.x * blockDim.x + threadIdx.x;
    if (r >= NN) return;
    float di = g_dinv[r];
    float sw = di * di;
    int b = g_is64 ? (int)((const long long*)batch)[r] : ((const int*)batch)[r];
    float* pool = g_pooled + (size_t)b * NH;
#pragma unroll
    for (int j4 = 0; j4 < 4; j4++) {
        float4 a = *(const float4*)(g_acc2 + (size_t)r * NH + 4 * j4);
        float4 p = *(const float4*)(g_hpre2 + (size_t)r * NH + 4 * j4);
        float4 v;
        v.x = fmaxf(fmaf(p.x, sw, a.x) + bs[4 * j4 + 0], 0.f);
        v.y = fmaxf(fmaf(p.y, sw, a.y) + bs[4 * j4 + 1], 0.f);
        v.z = fmaxf(fmaf(p.z, sw, a.z) + bs[4 * j4 + 2], 0.f);
        v.w = fmaxf(fmaf(p.w, sw, a.w) + bs[4 * j4 + 3], 0.f);
        red4(pool + 4 * j4, v);
    }
}

// ---- MLP head ----
__global__ void k_head(const float* __restrict__ lw1, const float* __restrict__ lb1,
                       const float* __restrict__ lw2, const float* __restrict__ lb2,
                       float* __restrict__ out) {
    __shared__ float w1s[NH * MH];
    __shared__ float w2s[MH * NC];
    __shared__ float b1s[MH];
    __shared__ float b2s[NC];
    for (int i = threadIdx.x; i < NH * MH; i += blockDim.x) w1s[i] = lw1[i];
    for (int i = threadIdx.x; i < MH * NC; i += blockDim.x) w2s[i] = lw2[i];
    if (threadIdx.x < MH) b1s[threadIdx.x] = lb1[threadIdx.x];
    if (threadIdx.x < NC) b2s[threadIdx.x] = lb2[threadIdx.x];
    __syncthreads();
    int g = blockIdx.x * blockDim.x + threadIdx.x;
    if (g >= NG) return;
    float p[NH];
#pragma unroll
    for (int j = 0; j < NH; j++) p[j] = fmaxf(g_pooled[g * NH + j], 0.f);
    float o[NC];
#pragma unroll
    for (int c = 0; c < NC; c++) o[c] = b2s[c];
    for (int m = 0; m < MH; m++) {
        float hh = b1s[m];
#pragma unroll
        for (int j = 0; j < NH; j++) hh += p[j] * w1s[j * MH + m];
        hh = fmaxf(hh, 0.f);
#pragma unroll
        for (int c = 0; c < NC; c++) o[c] += hh * w2s[m * NC + c];
    }
#pragma unroll
    for (int c = 0; c < NC; c++) out[g * NC + c] = o[c];
}

extern "C" void kernel_launch(void* const* d_in, const int* in_sizes, int n_in,
                              void* d_out, int out_size) {
    const float* x = nullptr;
    const void*  ei = nullptr;
    const void*  batch = nullptr;
    const float *W1 = nullptr, *b1 = nullptr, *W2 = nullptr, *b2 = nullptr;
    const float *lw1 = nullptr, *lb1 = nullptr, *lw2 = nullptr, *lb2 = nullptr;
    for (int i = 0; i < n_in; i++) {
        int sz = in_sizes[i];
        const void* p = d_in[i];
        switch (sz) {
            case NN * NF:   x     = (const float*)p; break;
            case 2 * NE:    ei    = p; break;
            case NN:        batch = p; break;
            case NF * NH:   W1    = (const float*)p; break;
            case NH * NH:   W2    = (const float*)p; break;
            case NH * MH:   lw1   = (const float*)p; break;
            case MH:        lb1   = (const float*)p; break;
            case MH * NC:   lw2   = (const float*)p; break;
            case NC:        lb2   = (const float*)p; break;
            case NH:        if (!b1) b1 = (const float*)p; else b2 = (const float*)p; break;
            default: break;
        }
    }
    float* out = (float*)d_out;

    k_detect<<<1, 1>>>((const int*)ei);
    k_zero<<<512, 256>>>();
    k_deg<<<(NE + 255) / 256, 256>>>(ei);
    k_scan1<<<NBLK, 256>>>();
    k_scan2<<<1, 512>>>();
    k_scan3<<<NBLK, 256>>>();
    k_dinv<<<NBLK, 256>>>();
    k_gemm1<<<NBLK, 256>>>(x, W1);
    k_fill<<<(NE + 255) / 256, 256>>>(ei);
    k_agg<1><<<(NN * 4 + 255) / 256, 256>>>();
    k_fin1<<<NBLK, 256>>>(b1, W2);
    k_agg<2><<<(NN * 4 + 255) / 256, 256>>>();
    k_fin2<<<NBLK, 256>>>(b2, batch);
    k_head<<<(NG + 255) / 256, 256>>>(lw1, lb1, lw2, lb2, out);
}